// round 3
// baseline (speedup 1.0000x reference)
#include <cuda_runtime.h>
#include <cstdint>

// Problem constants (fixed shapes from setup_inputs)
#define BB   16
#define NN   1536
#define CC   768
#define N0   3072
#define HH   64
#define WW   48
#define HW   (HH*WW)            // 3072
#define NPTS (BB*N0)            // 49,152
#define EPSF 1e-6f

// Chunked pipeline: CHUNKB batches at a time so slabs stay L2-resident
#define CHUNKB 4
#define NCHUNK (BB/CHUNKB)
#define SLAB   (CHUNKB*HW*CC)   // 9,437,184 floats = 37.75 MB

// Conv tiling
#define CH   16                 // channels per conv block (4 float4)
#define TY   8                  // output rows per conv block

// ---------------- device scratch (allocation-free) ----------------
__device__ __align__(16) float g_raw [SLAB];     // normalized token2map slab
__device__ __align__(16) float g_cv  [SLAB];     // post-conv slab
__device__ __align__(16) float g_wsum[BB*NN];    // sum(agg_w) -> 1/(sum+eps)
__device__ __align__(16) float g_wT  [9*CC];     // conv weights transposed [k][C]

__device__ int g_ppix   [NPTS];                  // pixel id per point
__device__ int g_pix_cnt[BB*HW];
__device__ int g_pix_off[BB*HW + 1];
__device__ int g_pix_cur[BB*HW];
__device__ int g_plist  [NPTS];                  // points sorted by pixel
__device__ int g_tok_cnt[BB*NN];
__device__ int g_tok_off[BB*NN + 1];
__device__ int g_tok_cur[BB*NN];
__device__ int g_tlist  [NPTS];                  // points sorted by token

// pixel coords matching jnp: pos = 0.5*(clip(loc,-1,1)+1)*wh - 0.5, unfused to match rounding
__device__ __forceinline__ float pix_coord(float l, float wh) {
    l = fminf(fmaxf(l, -1.0f), 1.0f);
    float t = __fmul_rn(0.5f, __fadd_rn(l, 1.0f));
    return __fadd_rn(__fmul_rn(t, wh), -0.5f);
}

// ---------------- zero the small metadata arrays ----------------
__global__ void k_zero_meta() {
    int i = blockIdx.x * blockDim.x + threadIdx.x;
    if (i < BB*HW) g_pix_cnt[i] = 0;
    if (i < BB*NN) { g_tok_cnt[i] = 0; g_wsum[i] = 0.0f; }
}

// ---------------- per-point counts ----------------
__global__ void k_count(const float* __restrict__ loc_orig,
                        const int*   __restrict__ idx_agg,
                        const float* __restrict__ agg_w) {
    int p = blockIdx.x * blockDim.x + threadIdx.x;
    if (p >= NPTS) return;
    int b = p / N0;
    float px = pix_coord(loc_orig[2*p],   (float)WW);
    float py = pix_coord(loc_orig[2*p+1], (float)HH);
    int ix = min(max((int)rintf(px), 0), WW-1);   // rintf = round-half-even = jnp.round
    int iy = min(max((int)rintf(py), 0), HH-1);
    int pix = b*HW + iy*WW + ix;
    g_ppix[p] = pix;
    atomicAdd(&g_pix_cnt[pix], 1);
    int seg = b*NN + idx_agg[p];
    atomicAdd(&g_tok_cnt[seg], 1);
    atomicAdd(&g_wsum[seg], agg_w[p]);
}

// ---------------- exclusive scans (block 0: pixels, block 1: tokens) ----------------
__global__ __launch_bounds__(1024) void k_scan() {
    __shared__ int sm[1024];
    int t = threadIdx.x;
    int n; int *cnt, *off, *cur;
    if (blockIdx.x == 0) { n = BB*HW; cnt = g_pix_cnt; off = g_pix_off; cur = g_pix_cur; }
    else                 { n = BB*NN; cnt = g_tok_cnt; off = g_tok_off; cur = g_tok_cur; }
    int chunk = (n + 1023) >> 10;
    int s = t * chunk, e = min(s + chunk, n);
    int tot = 0;
    for (int i = s; i < e; i++) tot += cnt[i];
    sm[t] = tot; __syncthreads();
    #pragma unroll
    for (int d = 1; d < 1024; d <<= 1) {
        int v = (t >= d) ? sm[t - d] : 0;
        __syncthreads();
        sm[t] += v;
        __syncthreads();
    }
    int base = sm[t] - tot;                 // exclusive prefix for this thread's range
    for (int i = s; i < e; i++) { off[i] = base; cur[i] = base; base += cnt[i]; }
    if (t == 1023) off[n] = sm[1023];
}

// ---------------- fill CSR point lists ----------------
__global__ void k_fill(const int* __restrict__ idx_agg) {
    int p = blockIdx.x * blockDim.x + threadIdx.x;
    if (p >= NPTS) return;
    int pix = g_ppix[p];
    int pos = atomicAdd(&g_pix_cur[pix], 1);
    g_plist[pos] = p;
    int b = p / N0;
    int seg = b*NN + idx_agg[p];
    int tp = atomicAdd(&g_tok_cur[seg], 1);
    g_tlist[tp] = p;
}

// ---------------- weight transpose + wsum reciprocal ----------------
__global__ void k_prep(const float* __restrict__ conv_w) {
    int i = blockIdx.x * blockDim.x + threadIdx.x;
    if (i < 9*CC) {
        int c = i / 9, k = i % 9;           // conv_w layout [C][1][3][3]
        g_wT[k*CC + c] = conv_w[i];
    } else if (i < 9*CC + BB*NN) {
        int j = i - 9*CC;
        g_wsum[j] = 1.0f / (g_wsum[j] + EPSF);
    }
}

// ---------------- scatter-as-gather: one block per pixel, no atomics ----------------
__global__ __launch_bounds__(192) void k_scatter_csr(const float* __restrict__ x,
                                                     const int*   __restrict__ idx_agg,
                                                     int chunk) {
    int lp = blockIdx.x;                    // local pixel in slab
    int gp = chunk*CHUNKB*HW + lp;          // global pixel
    int s = g_pix_off[gp], e = g_pix_off[gp+1];
    int b = gp / HW;
    int c4 = threadIdx.x;                   // 192 = CC/4
    float4 acc = make_float4(0.f, 0.f, 0.f, 0.f);
    for (int i = s; i < e; i++) {
        int p = g_plist[i];
        const float4* row = (const float4*)(x + ((size_t)b*NN + idx_agg[p])*CC);
        float4 v = __ldg(&row[c4]);
        acc.x += v.x; acc.y += v.y; acc.z += v.z; acc.w += v.w;
    }
    float rc = 1.0f / ((float)(e - s) + EPSF);
    acc.x *= rc; acc.y *= rc; acc.z *= rc; acc.w *= rc;
    ((float4*)(g_raw + (size_t)lp*CC))[c4] = acc;
}

// ---------------- tiled depthwise 3x3 conv on the slab ----------------
__global__ __launch_bounds__(192) void k_conv(const float* __restrict__ conv_b) {
    __shared__ float4 sm[(TY+2)*WW*(CH/4)];   // 30 KB
    const int ty0   = blockIdx.x * TY;
    const int cbase = blockIdx.y * CH;
    const int bl    = blockIdx.z;             // batch-local in chunk
    const int tid   = threadIdx.x;

    for (int idx = tid; idx < (TY+2)*WW*(CH/4); idx += 192) {
        int c4  = idx & 3;
        int pix = idx >> 2;
        int xx  = pix % WW;
        int row = pix / WW;
        int gy  = ty0 + row - 1;
        float4 v = make_float4(0.f, 0.f, 0.f, 0.f);
        if (gy >= 0 && gy < HH)
            v = *(const float4*)(g_raw + (size_t)(bl*HW + gy*WW + xx)*CC + cbase + 4*c4);
        sm[idx] = v;
    }
    __syncthreads();

    const int c4 = tid & 3;
    const int xx = tid >> 2;

    float4 w[9];
    #pragma unroll
    for (int k = 0; k < 9; k++)
        w[k] = *(const float4*)(g_wT + k*CC + cbase + 4*c4);
    const float4 bias = *(const float4*)(conv_b + cbase + 4*c4);

    float4 L[3], M[3], R[3];
    const bool hasL = (xx > 0), hasR = (xx < WW-1);
    float4 z = make_float4(0.f, 0.f, 0.f, 0.f);
    #pragma unroll
    for (int r = 0; r < 3; r++) {
        L[r] = hasL ? sm[(r*WW + xx-1)*4 + c4] : z;
        M[r] =        sm[(r*WW + xx  )*4 + c4];
        R[r] = hasR ? sm[(r*WW + xx+1)*4 + c4] : z;
    }

    #pragma unroll
    for (int oy = 0; oy < TY; oy++) {
        float4 acc = bias;
        #pragma unroll
        for (int r = 0; r < 3; r++) {
            acc.x += L[r].x*w[r*3+0].x + M[r].x*w[r*3+1].x + R[r].x*w[r*3+2].x;
            acc.y += L[r].y*w[r*3+0].y + M[r].y*w[r*3+1].y + R[r].y*w[r*3+2].y;
            acc.z += L[r].z*w[r*3+0].z + M[r].z*w[r*3+1].z + R[r].z*w[r*3+2].z;
            acc.w += L[r].w*w[r*3+0].w + M[r].w*w[r*3+1].w + R[r].w*w[r*3+2].w;
        }
        *(float4*)(g_cv + (size_t)(bl*HW + (ty0+oy)*WW + xx)*CC + cbase + 4*c4) = acc;
        if (oy < TY-1) {
            int r = oy + 3;
            L[0]=L[1]; L[1]=L[2]; L[2] = hasL ? sm[(r*WW + xx-1)*4 + c4] : z;
            M[0]=M[1]; M[1]=M[2]; M[2] =        sm[(r*WW + xx  )*4 + c4];
            R[0]=R[1]; R[1]=R[2]; R[2] = hasR ? sm[(r*WW + xx+1)*4 + c4] : z;
        }
    }
}

// ---------------- token gather: one block per token, no atomics ----------------
__global__ __launch_bounds__(192) void k_gather_csr(const float* __restrict__ loc_orig,
                                                    const float* __restrict__ agg_w,
                                                    float*       __restrict__ out,
                                                    int chunk) {
    int lt = blockIdx.x;                    // local token in chunk
    int gt = chunk*CHUNKB*NN + lt;          // global token segment
    int s = g_tok_off[gt], e = g_tok_off[gt+1];
    int bl = lt / NN;                       // batch-local
    float rw = g_wsum[gt];                  // 1/(sum+eps)
    int c4 = threadIdx.x;
    float4 acc = make_float4(0.f, 0.f, 0.f, 0.f);
    for (int i = s; i < e; i++) {
        int p = g_tlist[i];
        float px = pix_coord(loc_orig[2*p],   (float)WW);
        float py = pix_coord(loc_orig[2*p+1], (float)HH);
        int x0 = min(max((int)floorf(px), 0), WW-1);
        int y0 = min(max((int)floorf(py), 0), HH-1);
        int x1 = min(x0 + 1, WW-1);
        int y1 = min(y0 + 1, HH-1);
        float wx = fminf((float)x1, px) - (float)x0;   // reference border quirk
        float wy = fminf((float)y1, py) - (float)y0;
        float sc = agg_w[p] * rw;
        float w00 = (1.0f-wx)*(1.0f-wy) * sc;
        float w10 = wx*(1.0f-wy)        * sc;
        float w01 = (1.0f-wx)*wy        * sc;
        float w11 = wx*wy               * sc;
        int base = bl*HW;
        const float4* f00 = (const float4*)(g_cv + (size_t)(base + y0*WW + x0)*CC);
        const float4* f10 = (const float4*)(g_cv + (size_t)(base + y0*WW + x1)*CC);
        const float4* f01 = (const float4*)(g_cv + (size_t)(base + y1*WW + x0)*CC);
        const float4* f11 = (const float4*)(g_cv + (size_t)(base + y1*WW + x1)*CC);
        float4 a = f00[c4], bq = f10[c4], cq = f01[c4], dq = f11[c4];
        acc.x += w00*a.x + w10*bq.x + w01*cq.x + w11*dq.x;
        acc.y += w00*a.y + w10*bq.y + w01*cq.y + w11*dq.y;
        acc.z += w00*a.z + w10*bq.z + w01*cq.z + w11*dq.z;
        acc.w += w00*a.w + w10*bq.w + w01*cq.w + w11*dq.w;
    }
    ((float4*)(out + (size_t)gt*CC))[c4] = acc;
}

// ---------------- launch ----------------
extern "C" void kernel_launch(void* const* d_in, const int* in_sizes, int n_in,
                              void* d_out, int out_size) {
    const float* x        = (const float*)d_in[0];
    const float* loc_orig = (const float*)d_in[2];
    const int*   idx_agg  = (const int*)  d_in[3];
    const float* agg_w    = (const float*)d_in[4];
    const float* conv_w   = (const float*)d_in[n_in-2];
    const float* conv_b   = (const float*)d_in[n_in-1];
    float* out = (float*)d_out;

    // metadata zero + counts + scans + CSR fill + prep
    k_zero_meta<<<(BB*HW + 255)/256, 256>>>();
    k_count<<<(NPTS + 255)/256, 256>>>(loc_orig, idx_agg, agg_w);
    k_scan<<<2, 1024>>>();
    k_fill<<<(NPTS + 255)/256, 256>>>(idx_agg);
    k_prep<<<(9*CC + BB*NN + 255)/256, 256>>>(conv_w);

    // chunked pipeline: slabs stay L2-resident across the three stages
    for (int c = 0; c < NCHUNK; c++) {
        k_scatter_csr<<<CHUNKB*HW, 192>>>(x, idx_agg, c);
        dim3 cgrid(HH/TY, CC/CH, CHUNKB);
        k_conv<<<cgrid, 192>>>(conv_b);
        k_gather_csr<<<CHUNKB*NN, 192>>>(loc_orig, agg_w, out, c);
    }
}